// round 14
// baseline (speedup 1.0000x reference)
#include <cuda_runtime.h>
#include <cstdint>

#define NO     20000
#define KC     11
#define DIM    256
#define OUTF   128
#define KSEL   10
#define NT     100000
#define NWARP  11
#define NTHR   352
#define SLOTS  4
#define AHEAD  3
#define ROWB   (KC * DIM * 4)     // 11264 bytes per candidate block
#define SELB   (KSEL * DIM * 4)   // 10240 bytes per output block

// ---- persistent scratch (no allocations allowed) ----
__device__ __align__(16) float g_wa2[2 * DIM];
__device__ __align__(8) float g_rowdot[NT];
__device__ __align__(8) float g_rowsum[NT];
__device__ double g_sumA;
__device__ double g_sumB;
__device__ unsigned int g_bar  = 0;
__device__ unsigned int g_done = 0;

__device__ __forceinline__ unsigned int ld_acquire(const unsigned int* p) {
    unsigned int v;
    asm volatile("ld.acquire.gpu.global.b32 %0, [%1];" : "=r"(v) : "l"(p));
    return v;
}
// release-ordered increment: orders prior STGs without CCTL.IVALL (no L1 flush)
__device__ __forceinline__ void red_release_add(unsigned int* p, unsigned int v) {
    asm volatile("red.release.gpu.global.add.u32 [%0], %1;" :: "l"(p), "r"(v) : "memory");
}
__device__ __forceinline__ unsigned int atom_acqrel_add(unsigned int* p, unsigned int v) {
    unsigned int old;
    asm volatile("atom.acq_rel.gpu.global.add.u32 %0, [%1], %2;" : "=r"(old) : "l"(p), "r"(v) : "memory");
    return old;
}
__device__ __forceinline__ void grid_barrier(unsigned int target) {
    __syncthreads();
    if (threadIdx.x == 0) {
        red_release_add(&g_bar, 1u);
        while (ld_acquire(&g_bar) < target) __nanosleep(64);
    }
    __syncthreads();
}

__device__ __forceinline__ uint32_t smem_u32(const void* p) {
    return (uint32_t)__cvta_generic_to_shared(p);
}
__device__ __forceinline__ void mb_init(uint32_t a, uint32_t cnt) {
    asm volatile("mbarrier.init.shared.b64 [%0], %1;" :: "r"(a), "r"(cnt) : "memory");
}
__device__ __forceinline__ void fence_async_shared() {
    asm volatile("fence.proxy.async.shared::cta;" ::: "memory");
}
__device__ __forceinline__ void mb_expect(uint32_t a, uint32_t bytes) {
    asm volatile("mbarrier.arrive.expect_tx.shared.b64 _, [%0], %1;" :: "r"(a), "r"(bytes) : "memory");
}
__device__ __forceinline__ void mb_wait(uint32_t a, uint32_t ph) {
    asm volatile(
        "{\n\t.reg .pred P;\n\t"
        "W_%=: mbarrier.try_wait.parity.acquire.cta.shared::cta.b64 P, [%0], %1, 0x989680;\n\t"
        "@P bra.uni D_%=;\n\t"
        "bra.uni W_%=;\n\t"
        "D_%=:\n\t}"
        :: "r"(a), "r"(ph) : "memory");
}
__device__ __forceinline__ void bulk_load(uint32_t sdst, const void* gsrc, uint32_t bytes, uint32_t mbar) {
    asm volatile("cp.async.bulk.shared::cta.global.mbarrier::complete_tx::bytes [%0], [%1], %2, [%3];"
                 :: "r"(sdst), "l"(gsrc), "r"(bytes), "r"(mbar) : "memory");
}
__device__ __forceinline__ void bulk_store(void* gdst, uint32_t ssrc, uint32_t bytes) {
    asm volatile("cp.async.bulk.global.shared::cta.bulk_group [%0], [%1], %2;"
                 :: "l"(gdst), "r"(ssrc), "r"(bytes) : "memory");
}
__device__ __forceinline__ void bulk_commit() {
    asm volatile("cp.async.bulk.commit_group;" ::: "memory");
}
__device__ __forceinline__ void bulk_wait_read1() {
    asm volatile("cp.async.bulk.wait_group.read 1;" ::: "memory");
}
__device__ __forceinline__ void bulk_wait_all() {
    asm volatile("cp.async.bulk.wait_group 0;" ::: "memory");
}

__global__ void __launch_bounds__(NTHR) fused_kernel(
    const float* __restrict__ Cand,     // [NO, KC, DIM]
    const float* __restrict__ ndist,    // [NO, KC]
    const int*   __restrict__ nind,     // [NO, KC]
    const float* __restrict__ dtrain,   // [NT, DIM]
    const float* __restrict__ W,        // [2*DIM, OUTF]
    const float* __restrict__ A,        // [2*OUTF]
    float*       __restrict__ out)
{
    __shared__ __align__(128) float buf[SLOTS][KC * DIM];     // 45056 B
    __shared__ float sScore[2][KC];
    __shared__ float sRow[2][KC];
    __shared__ int   sInd[2][KC];
    __shared__ __align__(8) unsigned long long mbar[SLOTS];

    const int tid  = threadIdx.x;
    const int w    = tid >> 5;
    const int lane = tid & 31;
    const int bid  = blockIdx.x;
    const int G    = gridDim.x;
    const int gwarp = bid * NWARP + w;
    const int gws   = G * NWARP;

    // rows for this CTA: n = bid + i*G, i in [0, cnt)
    const int cnt = (NO - bid + G - 1) / G;

    // ---- earliest possible TMA prolog: candidate loads depend on nothing ----
    if (tid == 0) {
#pragma unroll
        for (int s = 0; s < SLOTS; ++s) mb_init(smem_u32(&mbar[s]), 1);
        fence_async_shared();
        const int pre = cnt < AHEAD ? cnt : AHEAD;
        for (int i = 0; i < pre; ++i) {
            const int n = bid + i * G;
            const uint32_t mb = smem_u32(&mbar[i]);
            mb_expect(mb, ROWB);
            bulk_load(smem_u32(&buf[i][0]), Cand + (size_t)n * KC * DIM, ROWB, mb);
        }
    }

    // ---- Phase 0: wa2 ----
    if (gwarp < 2 * DIM) {
        const float* wrow = W + (size_t)gwarp * OUTF;
        const float* a2   = A + OUTF;
        float acc = wrow[lane]      * a2[lane]
                  + wrow[lane + 32] * a2[lane + 32]
                  + wrow[lane + 64] * a2[lane + 64]
                  + wrow[lane + 96] * a2[lane + 96];
#pragma unroll
        for (int off = 16; off; off >>= 1)
            acc += __shfl_down_sync(0xffffffffu, acc, off);
        if (lane == 0) g_wa2[gwarp] = acc;
    }
    if (bid == 0 && tid == 0) {
        atomicExch((unsigned long long*)&g_sumA, 0ull);
        atomicExch((unsigned long long*)&g_sumB, 0ull);
    }

    grid_barrier(G);

    // loop-invariant weight registers (wa2_lo for phase 2, wa2_hi for phase 1)
    const float4* w4g = (const float4*)g_wa2;
    float4 wl0 = w4g[lane],      wl1 = w4g[lane + 32];
    float4 wh0 = w4g[lane + 64], wh1 = w4g[lane + 96];

    // ---- Phase 1: streaming table scan, 2 rows per warp per iteration ----
    // (4 independent LDG.128 in flight; two interleaved shfl chains; float2 stores)
    for (int base = gwarp * 2; base < NT; base += gws * 2) {
        const float4* dp0 = (const float4*)(dtrain + (size_t)base * DIM);
        const float4* dp1 = (const float4*)(dtrain + (size_t)(base + 1) * DIM);
        float4 a0 = dp0[lane], b0 = dp0[lane + 32];
        float4 a1 = dp1[lane], b1 = dp1[lane + 32];

        float dot0 = a0.x*wh0.x + a0.y*wh0.y + a0.z*wh0.z + a0.w*wh0.w
                   + b0.x*wh1.x + b0.y*wh1.y + b0.z*wh1.z + b0.w*wh1.w;
        float dot1 = a1.x*wh0.x + a1.y*wh0.y + a1.z*wh0.z + a1.w*wh0.w
                   + b1.x*wh1.x + b1.y*wh1.y + b1.z*wh1.z + b1.w*wh1.w;
        float sum0 = a0.x + a0.y + a0.z + a0.w + b0.x + b0.y + b0.z + b0.w;
        float sum1 = a1.x + a1.y + a1.z + a1.w + b1.x + b1.y + b1.z + b1.w;

#pragma unroll
        for (int off = 16; off; off >>= 1) {
            dot0 += __shfl_down_sync(0xffffffffu, dot0, off);
            dot1 += __shfl_down_sync(0xffffffffu, dot1, off);
            sum0 += __shfl_down_sync(0xffffffffu, sum0, off);
            sum1 += __shfl_down_sync(0xffffffffu, sum1, off);
        }
        if (lane == 0) {
            *(float2*)&g_rowdot[base] = make_float2(dot0, dot1);
            *(float2*)&g_rowsum[base] = make_float2(sum0, sum1);
        }
    }

    grid_barrier(2u * G);               // rowdot/rowsum visible

    // ---- Phase 2: pipelined main loop ----
    const size_t ND_OFF = (size_t)NO * KSEL * DIM;
    const size_t NI_OFF = ND_OFF + (size_t)NO * KSEL;
    double lsumA = 0.0, lsumB = 0.0;

    for (int i = 0; i < cnt; ++i) {
        const int n    = bid + i * G;
        const int slot = i & (SLOTS - 1);
        const int ph   = (i >> 2) & 1;
        const int b    = i & 1;

        // prefetch table scalars before the wait
        float rdot = 0.f, rsum = 0.f;
        int   ind  = 0;
        if (lane == 0) {
            ind  = __ldg(nind + n * KC + w);
            rdot = g_rowdot[ind];
            rsum = g_rowsum[ind];
        }

        mb_wait(smem_u32(&mbar[slot]), ph);

        const float4* bp = (const float4*)&buf[slot][w * DIM];
        float4 c0 = bp[lane], c1 = bp[lane + 32];

        float sc = c0.x*wl0.x + c0.y*wl0.y + c0.z*wl0.z + c0.w*wl0.w
                 + c1.x*wl1.x + c1.y*wl1.y + c1.z*wl1.z + c1.w*wl1.w;
#pragma unroll
        for (int off = 16; off; off >>= 1)
            sc += __shfl_down_sync(0xffffffffu, sc, off);
        if (lane == 0) {
            sScore[b][w] = sc + rdot;
            sRow[b][w]   = rsum;
            sInd[b][w]   = ind;
        }

        __syncthreads();

        // only the store thread and the tail warp consume `drop`
        if (tid == 0 || w == NWARP - 1) {
            float minv = sScore[b][0];
            int   drop = 0;
#pragma unroll
            for (int kk = 1; kk < KC; ++kk) {
                float v = sScore[b][kk];
                if (v <= minv) { minv = v; drop = kk; }
            }

            if (tid == 0) {
                // bulk stores: prefix [0, drop) rows, suffix (drop, KC) rows
                char* gdst = (char*)out + (size_t)n * SELB;
                const uint32_t src = smem_u32(&buf[slot][0]);
                const uint32_t pb  = (uint32_t)drop * DIM * 4;
                const uint32_t sb  = (uint32_t)(KSEL - drop) * DIM * 4;
                if (pb) bulk_store(gdst, src, pb);
                if (sb) bulk_store(gdst + pb, src + pb + DIM * 4, sb);
                bulk_commit();
                // reuse safety: the slot loaded next was stored at iter i-1 (one group back)
                bulk_wait_read1();
                const int ip = i + AHEAD;
                if (ip < cnt) {
                    const int np = bid + ip * G;
                    const int sl = ip & (SLOTS - 1);
                    const uint32_t mb = smem_u32(&mbar[sl]);
                    mb_expect(mb, ROWB);
                    bulk_load(smem_u32(&buf[sl][0]), Cand + (size_t)np * KC * DIM, ROWB, mb);
                }
            } else {
                if (lane < KSEL) {
                    const int src = lane + (lane >= drop ? 1 : 0);
                    out[ND_OFF + (size_t)n * KSEL + lane] = ndist[n * KC + src];
                    out[NI_OFF + (size_t)n * KSEL + lane] = (float)sInd[b][src];
                } else if (lane == KSEL) {
                    float sa = 0.f;
#pragma unroll
                    for (int kk = 0; kk < KC; ++kk) if (kk != drop) sa += sRow[b][kk];
                    lsumA += (double)sa;
                    lsumB += (double)sRow[b][drop];
                }
            }
        }
    }

    if (tid == 0) bulk_wait_all();      // all bulk stores drained

    if (w == NWARP - 1 && lane == KSEL) {
        atomicAdd(&g_sumA, lsumA);
        atomicAdd(&g_sumB, lsumB);
    }

    // ---- epilog: last CTA writes scalars + resets barrier state ----
    __syncthreads();
    if (tid == 0) {
        // acq_rel increment: orders the sum atomics above without an L1 flush
        unsigned int prev = atom_acqrel_add(&g_done, 1u);
        if (prev == (unsigned)G - 1) {
            double sA = atomicAdd(&g_sumA, 0.0);
            double sB = atomicAdd(&g_sumB, 0.0);
            const size_t A_OFF = (size_t)NO * KSEL * DIM + 2ull * NO * KSEL;
            out[A_OFF]     = (float)(sA / ((double)NO * KSEL));
            out[A_OFF + 1] = (float)(sB / (double)NO);
            atomicExch(&g_bar, 0u);
            atomicExch(&g_done, 0u);
        }
    }
}

extern "C" void kernel_launch(void* const* d_in, const int* in_sizes, int n_in,
                              void* d_out, int out_size) {
    (void)out_size;
    const float* Cand   = nullptr;
    const float* ndist  = nullptr;
    const int*   nind   = nullptr;
    const float* dtrain = nullptr;
    const float* W      = nullptr;
    const float* A      = nullptr;
    for (int i = 0; i < n_in; ++i) {
        const int s = in_sizes[i];
        if      (s == 56320000) Cand   = (const float*)d_in[i];
        else if (s == 25600000) dtrain = (const float*)d_in[i];
        else if (s == 220000) {
            if (!ndist) ndist = (const float*)d_in[i];
            else        nind  = (const int*)d_in[i];
        }
        else if (s == 65536)    W      = (const float*)d_in[i];
        else if (s == 256)      A      = (const float*)d_in[i];
    }
    float* out = (float*)d_out;

    int dev = 0, nsm = 148, perSM = 0;
    cudaGetDevice(&dev);
    cudaDeviceGetAttribute(&nsm, cudaDevAttrMultiProcessorCount, dev);
    cudaOccupancyMaxActiveBlocksPerMultiprocessor(&perSM, fused_kernel, NTHR, 0);
    if (perSM < 1) perSM = 1;
    int grid = nsm * perSM;
    if (grid > NO) grid = NO;

    fused_kernel<<<grid, NTHR>>>(Cand, ndist, nind, dtrain, W, A, out);
}

// round 15
// speedup vs baseline: 1.0480x; 1.0480x over previous
#include <cuda_runtime.h>
#include <cstdint>

#define NO     20000
#define KC     11
#define DIM    256
#define OUTF   128
#define KSEL   10
#define NT     100000
#define NWARP  11
#define NTHR   352
#define SLOTS  4
#define AHEAD  3
#define ROWB   (KC * DIM * 4)     // 11264 bytes per candidate block
#define SELB   (KSEL * DIM * 4)   // 10240 bytes per output block

// ---- persistent scratch (no allocations allowed) ----
__device__ __align__(16) float g_wa2[2 * DIM];
__device__ __align__(8) float g_rowdot[NT];
__device__ __align__(8) float g_rowsum[NT];
__device__ double g_sumA;
__device__ double g_sumB;
__device__ unsigned int g_bar  = 0;
__device__ unsigned int g_done = 0;

__device__ __forceinline__ unsigned int ld_acquire(const unsigned int* p) {
    unsigned int v;
    asm volatile("ld.acquire.gpu.global.b32 %0, [%1];" : "=r"(v) : "l"(p));
    return v;
}
// release-ordered increment: orders prior STGs without CCTL.IVALL (no L1 flush)
__device__ __forceinline__ void red_release_add(unsigned int* p, unsigned int v) {
    asm volatile("red.release.gpu.global.add.u32 [%0], %1;" :: "l"(p), "r"(v) : "memory");
}
__device__ __forceinline__ unsigned int atom_acqrel_add(unsigned int* p, unsigned int v) {
    unsigned int old;
    asm volatile("atom.acq_rel.gpu.global.add.u32 %0, [%1], %2;" : "=r"(old) : "l"(p), "r"(v) : "memory");
    return old;
}
__device__ __forceinline__ void grid_barrier(unsigned int target) {
    __syncthreads();
    if (threadIdx.x == 0) {
        red_release_add(&g_bar, 1u);
        while (ld_acquire(&g_bar) < target) __nanosleep(64);
    }
    __syncthreads();
}

__device__ __forceinline__ uint32_t smem_u32(const void* p) {
    return (uint32_t)__cvta_generic_to_shared(p);
}
__device__ __forceinline__ void mb_init(uint32_t a, uint32_t cnt) {
    asm volatile("mbarrier.init.shared.b64 [%0], %1;" :: "r"(a), "r"(cnt) : "memory");
}
__device__ __forceinline__ void fence_async_shared() {
    asm volatile("fence.proxy.async.shared::cta;" ::: "memory");
}
__device__ __forceinline__ void mb_expect(uint32_t a, uint32_t bytes) {
    asm volatile("mbarrier.arrive.expect_tx.shared.b64 _, [%0], %1;" :: "r"(a), "r"(bytes) : "memory");
}
__device__ __forceinline__ void mb_wait(uint32_t a, uint32_t ph) {
    asm volatile(
        "{\n\t.reg .pred P;\n\t"
        "W_%=: mbarrier.try_wait.parity.acquire.cta.shared::cta.b64 P, [%0], %1, 0x989680;\n\t"
        "@P bra.uni D_%=;\n\t"
        "bra.uni W_%=;\n\t"
        "D_%=:\n\t}"
        :: "r"(a), "r"(ph) : "memory");
}
__device__ __forceinline__ void bulk_load(uint32_t sdst, const void* gsrc, uint32_t bytes, uint32_t mbar) {
    asm volatile("cp.async.bulk.shared::cta.global.mbarrier::complete_tx::bytes [%0], [%1], %2, [%3];"
                 :: "r"(sdst), "l"(gsrc), "r"(bytes), "r"(mbar) : "memory");
}
__device__ __forceinline__ void bulk_store(void* gdst, uint32_t ssrc, uint32_t bytes) {
    asm volatile("cp.async.bulk.global.shared::cta.bulk_group [%0], [%1], %2;"
                 :: "l"(gdst), "r"(ssrc), "r"(bytes) : "memory");
}
__device__ __forceinline__ void bulk_commit() {
    asm volatile("cp.async.bulk.commit_group;" ::: "memory");
}
__device__ __forceinline__ void bulk_wait_read1() {
    asm volatile("cp.async.bulk.wait_group.read 1;" ::: "memory");
}
__device__ __forceinline__ void bulk_wait_all() {
    asm volatile("cp.async.bulk.wait_group 0;" ::: "memory");
}

__global__ void __launch_bounds__(NTHR, 4) fused_kernel(
    const float* __restrict__ Cand,     // [NO, KC, DIM]
    const float* __restrict__ ndist,    // [NO, KC]
    const int*   __restrict__ nind,     // [NO, KC]
    const float* __restrict__ dtrain,   // [NT, DIM]
    const float* __restrict__ W,        // [2*DIM, OUTF]
    const float* __restrict__ A,        // [2*OUTF]
    float*       __restrict__ out)
{
    __shared__ __align__(128) float buf[SLOTS][KC * DIM];     // 45056 B
    __shared__ float sScore[2][KC];
    __shared__ float sRow[2][KC];
    __shared__ int   sInd[2][KC];
    __shared__ __align__(8) unsigned long long mbar[SLOTS];

    const int tid  = threadIdx.x;
    const int w    = tid >> 5;
    const int lane = tid & 31;
    const int bid  = blockIdx.x;
    const int G    = gridDim.x;
    const int gwarp = bid * NWARP + w;
    const int gws   = G * NWARP;

    // rows for this CTA: n = bid + i*G, i in [0, cnt)
    const int cnt = (NO - bid + G - 1) / G;

    // ---- earliest possible TMA prolog: candidate loads depend on nothing ----
    if (tid == 0) {
#pragma unroll
        for (int s = 0; s < SLOTS; ++s) mb_init(smem_u32(&mbar[s]), 1);
        fence_async_shared();
        const int pre = cnt < AHEAD ? cnt : AHEAD;
        for (int i = 0; i < pre; ++i) {
            const int n = bid + i * G;
            const uint32_t mb = smem_u32(&mbar[i]);
            mb_expect(mb, ROWB);
            bulk_load(smem_u32(&buf[i][0]), Cand + (size_t)n * KC * DIM, ROWB, mb);
        }
    }

    // ---- Phase 0: wa2 ----
    if (gwarp < 2 * DIM) {
        const float* wrow = W + (size_t)gwarp * OUTF;
        const float* a2   = A + OUTF;
        float acc = wrow[lane]      * a2[lane]
                  + wrow[lane + 32] * a2[lane + 32]
                  + wrow[lane + 64] * a2[lane + 64]
                  + wrow[lane + 96] * a2[lane + 96];
#pragma unroll
        for (int off = 16; off; off >>= 1)
            acc += __shfl_down_sync(0xffffffffu, acc, off);
        if (lane == 0) g_wa2[gwarp] = acc;
    }
    if (bid == 0 && tid == 0) {
        atomicExch((unsigned long long*)&g_sumA, 0ull);
        atomicExch((unsigned long long*)&g_sumB, 0ull);
    }

    grid_barrier(G);

    // loop-invariant weight registers (wa2_lo for phase 2, wa2_hi for phase 1)
    const float4* w4g = (const float4*)g_wa2;
    float4 wl0 = w4g[lane],      wl1 = w4g[lane + 32];
    float4 wh0 = w4g[lane + 64], wh1 = w4g[lane + 96];

    // ---- Phase 1: streaming table scan, 2 rows per warp per iteration ----
    // (4 independent LDG.128 in flight; two interleaved shfl chains; float2 stores)
    for (int base = gwarp * 2; base < NT; base += gws * 2) {
        const float4* dp0 = (const float4*)(dtrain + (size_t)base * DIM);
        const float4* dp1 = (const float4*)(dtrain + (size_t)(base + 1) * DIM);
        float4 a0 = dp0[lane], b0 = dp0[lane + 32];
        float4 a1 = dp1[lane], b1 = dp1[lane + 32];

        float dot0 = a0.x*wh0.x + a0.y*wh0.y + a0.z*wh0.z + a0.w*wh0.w
                   + b0.x*wh1.x + b0.y*wh1.y + b0.z*wh1.z + b0.w*wh1.w;
        float dot1 = a1.x*wh0.x + a1.y*wh0.y + a1.z*wh0.z + a1.w*wh0.w
                   + b1.x*wh1.x + b1.y*wh1.y + b1.z*wh1.z + b1.w*wh1.w;
        float sum0 = a0.x + a0.y + a0.z + a0.w + b0.x + b0.y + b0.z + b0.w;
        float sum1 = a1.x + a1.y + a1.z + a1.w + b1.x + b1.y + b1.z + b1.w;

#pragma unroll
        for (int off = 16; off; off >>= 1) {
            dot0 += __shfl_down_sync(0xffffffffu, dot0, off);
            dot1 += __shfl_down_sync(0xffffffffu, dot1, off);
            sum0 += __shfl_down_sync(0xffffffffu, sum0, off);
            sum1 += __shfl_down_sync(0xffffffffu, sum1, off);
        }
        if (lane == 0) {
            *(float2*)&g_rowdot[base] = make_float2(dot0, dot1);
            *(float2*)&g_rowsum[base] = make_float2(sum0, sum1);
        }
    }

    grid_barrier(2u * G);               // rowdot/rowsum visible

    // ---- Phase 2: pipelined main loop ----
    const size_t ND_OFF = (size_t)NO * KSEL * DIM;
    const size_t NI_OFF = ND_OFF + (size_t)NO * KSEL;
    double lsumA = 0.0, lsumB = 0.0;

    for (int i = 0; i < cnt; ++i) {
        const int n    = bid + i * G;
        const int slot = i & (SLOTS - 1);
        const int ph   = (i >> 2) & 1;
        const int b    = i & 1;

        // prefetch table scalars before the wait
        float rdot = 0.f, rsum = 0.f;
        int   ind  = 0;
        if (lane == 0) {
            ind  = __ldg(nind + n * KC + w);
            rdot = g_rowdot[ind];
            rsum = g_rowsum[ind];
        }

        mb_wait(smem_u32(&mbar[slot]), ph);

        const float4* bp = (const float4*)&buf[slot][w * DIM];
        float4 c0 = bp[lane], c1 = bp[lane + 32];

        float sc = c0.x*wl0.x + c0.y*wl0.y + c0.z*wl0.z + c0.w*wl0.w
                 + c1.x*wl1.x + c1.y*wl1.y + c1.z*wl1.z + c1.w*wl1.w;
#pragma unroll
        for (int off = 16; off; off >>= 1)
            sc += __shfl_down_sync(0xffffffffu, sc, off);
        if (lane == 0) {
            sScore[b][w] = sc + rdot;
            sRow[b][w]   = rsum;
            sInd[b][w]   = ind;
        }

        __syncthreads();

        // only the store thread and the tail warp consume `drop`
        if (tid == 0 || w == NWARP - 1) {
            float minv = sScore[b][0];
            int   drop = 0;
#pragma unroll
            for (int kk = 1; kk < KC; ++kk) {
                float v = sScore[b][kk];
                if (v <= minv) { minv = v; drop = kk; }
            }

            if (tid == 0) {
                // bulk stores: prefix [0, drop) rows, suffix (drop, KC) rows
                char* gdst = (char*)out + (size_t)n * SELB;
                const uint32_t src = smem_u32(&buf[slot][0]);
                const uint32_t pb  = (uint32_t)drop * DIM * 4;
                const uint32_t sb  = (uint32_t)(KSEL - drop) * DIM * 4;
                if (pb) bulk_store(gdst, src, pb);
                if (sb) bulk_store(gdst + pb, src + pb + DIM * 4, sb);
                bulk_commit();
                // reuse safety: the slot loaded next was stored at iter i-1 (one group back)
                bulk_wait_read1();
                const int ip = i + AHEAD;
                if (ip < cnt) {
                    const int np = bid + ip * G;
                    const int sl = ip & (SLOTS - 1);
                    const uint32_t mb = smem_u32(&mbar[sl]);
                    mb_expect(mb, ROWB);
                    bulk_load(smem_u32(&buf[sl][0]), Cand + (size_t)np * KC * DIM, ROWB, mb);
                }
            } else {
                if (lane < KSEL) {
                    const int src = lane + (lane >= drop ? 1 : 0);
                    out[ND_OFF + (size_t)n * KSEL + lane] = ndist[n * KC + src];
                    out[NI_OFF + (size_t)n * KSEL + lane] = (float)sInd[b][src];
                } else if (lane == KSEL) {
                    float sa = 0.f;
#pragma unroll
                    for (int kk = 0; kk < KC; ++kk) if (kk != drop) sa += sRow[b][kk];
                    lsumA += (double)sa;
                    lsumB += (double)sRow[b][drop];
                }
            }
        }
    }

    if (tid == 0) bulk_wait_all();      // all bulk stores drained

    if (w == NWARP - 1 && lane == KSEL) {
        atomicAdd(&g_sumA, lsumA);
        atomicAdd(&g_sumB, lsumB);
    }

    // ---- epilog: last CTA writes scalars + resets barrier state ----
    __syncthreads();
    if (tid == 0) {
        // acq_rel increment: orders the sum atomics above without an L1 flush
        unsigned int prev = atom_acqrel_add(&g_done, 1u);
        if (prev == (unsigned)G - 1) {
            double sA = atomicAdd(&g_sumA, 0.0);
            double sB = atomicAdd(&g_sumB, 0.0);
            const size_t A_OFF = (size_t)NO * KSEL * DIM + 2ull * NO * KSEL;
            out[A_OFF]     = (float)(sA / ((double)NO * KSEL));
            out[A_OFF + 1] = (float)(sB / (double)NO);
            atomicExch(&g_bar, 0u);
            atomicExch(&g_done, 0u);
        }
    }
}

extern "C" void kernel_launch(void* const* d_in, const int* in_sizes, int n_in,
                              void* d_out, int out_size) {
    (void)out_size;
    const float* Cand   = nullptr;
    const float* ndist  = nullptr;
    const int*   nind   = nullptr;
    const float* dtrain = nullptr;
    const float* W      = nullptr;
    const float* A      = nullptr;
    for (int i = 0; i < n_in; ++i) {
        const int s = in_sizes[i];
        if      (s == 56320000) Cand   = (const float*)d_in[i];
        else if (s == 25600000) dtrain = (const float*)d_in[i];
        else if (s == 220000) {
            if (!ndist) ndist = (const float*)d_in[i];
            else        nind  = (const int*)d_in[i];
        }
        else if (s == 65536)    W      = (const float*)d_in[i];
        else if (s == 256)      A      = (const float*)d_in[i];
    }
    float* out = (float*)d_out;

    int dev = 0, nsm = 148, perSM = 0;
    cudaGetDevice(&dev);
    cudaDeviceGetAttribute(&nsm, cudaDevAttrMultiProcessorCount, dev);
    cudaOccupancyMaxActiveBlocksPerMultiprocessor(&perSM, fused_kernel, NTHR, 0);
    if (perSM < 1) perSM = 1;
    int grid = nsm * perSM;
    if (grid > NO) grid = NO;

    fused_kernel<<<grid, NTHR>>>(Cand, ndist, nind, dtrain, W, A, out);
}

// round 16
// speedup vs baseline: 1.0526x; 1.0044x over previous
#include <cuda_runtime.h>
#include <cstdint>

#define NO     20000
#define KC     11
#define DIM    256
#define OUTF   128
#define KSEL   10
#define NT     100000
#define NWARP  11
#define NTHR   352
#define SLOTS  4
#define AHEAD  3
#define ROWB   (KC * DIM * 4)     // 11264 bytes per candidate block
#define SELB   (KSEL * DIM * 4)   // 10240 bytes per output block

// ---- persistent scratch (no allocations allowed) ----
__device__ __align__(16) float g_wa2[2 * DIM];
__device__ float  g_rowdot[NT];
__device__ float  g_rowsum[NT];
__device__ double g_sumA;
__device__ double g_sumB;
__device__ unsigned int g_bar  = 0;
__device__ unsigned int g_done = 0;

__device__ __forceinline__ unsigned int ld_acquire(const unsigned int* p) {
    unsigned int v;
    asm volatile("ld.acquire.gpu.global.b32 %0, [%1];" : "=r"(v) : "l"(p));
    return v;
}
// release-ordered increment: orders prior STGs without CCTL.IVALL (no L1 flush)
__device__ __forceinline__ void red_release_add(unsigned int* p, unsigned int v) {
    asm volatile("red.release.gpu.global.add.u32 [%0], %1;" :: "l"(p), "r"(v) : "memory");
}
__device__ __forceinline__ unsigned int atom_acqrel_add(unsigned int* p, unsigned int v) {
    unsigned int old;
    asm volatile("atom.acq_rel.gpu.global.add.u32 %0, [%1], %2;" : "=r"(old) : "l"(p), "r"(v) : "memory");
    return old;
}
__device__ __forceinline__ void grid_barrier(unsigned int target) {
    __syncthreads();
    if (threadIdx.x == 0) {
        red_release_add(&g_bar, 1u);
        while (ld_acquire(&g_bar) < target) __nanosleep(64);
    }
    __syncthreads();
}

__device__ __forceinline__ uint32_t smem_u32(const void* p) {
    return (uint32_t)__cvta_generic_to_shared(p);
}
__device__ __forceinline__ void mb_init(uint32_t a, uint32_t cnt) {
    asm volatile("mbarrier.init.shared.b64 [%0], %1;" :: "r"(a), "r"(cnt) : "memory");
}
__device__ __forceinline__ void fence_async_shared() {
    asm volatile("fence.proxy.async.shared::cta;" ::: "memory");
}
__device__ __forceinline__ void mb_expect(uint32_t a, uint32_t bytes) {
    asm volatile("mbarrier.arrive.expect_tx.shared.b64 _, [%0], %1;" :: "r"(a), "r"(bytes) : "memory");
}
__device__ __forceinline__ void mb_wait(uint32_t a, uint32_t ph) {
    asm volatile(
        "{\n\t.reg .pred P;\n\t"
        "W_%=: mbarrier.try_wait.parity.acquire.cta.shared::cta.b64 P, [%0], %1, 0x989680;\n\t"
        "@P bra.uni D_%=;\n\t"
        "bra.uni W_%=;\n\t"
        "D_%=:\n\t}"
        :: "r"(a), "r"(ph) : "memory");
}
// evict_first L2 policy: streaming data (read-once / write-once)
__device__ __forceinline__ uint64_t make_policy_evict_first() {
    uint64_t pol;
    asm volatile("createpolicy.fractional.L2::evict_first.b64 %0, 1.0;" : "=l"(pol));
    return pol;
}
__device__ __forceinline__ void bulk_load_pol(uint32_t sdst, const void* gsrc, uint32_t bytes,
                                              uint32_t mbar, uint64_t pol) {
    asm volatile("cp.async.bulk.shared::cta.global.mbarrier::complete_tx::bytes.L2::cache_hint "
                 "[%0], [%1], %2, [%3], %4;"
                 :: "r"(sdst), "l"(gsrc), "r"(bytes), "r"(mbar), "l"(pol) : "memory");
}
__device__ __forceinline__ void bulk_store_pol(void* gdst, uint32_t ssrc, uint32_t bytes, uint64_t pol) {
    asm volatile("cp.async.bulk.global.shared::cta.bulk_group.L2::cache_hint [%0], [%1], %2, %3;"
                 :: "l"(gdst), "r"(ssrc), "r"(bytes), "l"(pol) : "memory");
}
__device__ __forceinline__ void bulk_commit() {
    asm volatile("cp.async.bulk.commit_group;" ::: "memory");
}
__device__ __forceinline__ void bulk_wait_read1() {
    asm volatile("cp.async.bulk.wait_group.read 1;" ::: "memory");
}
__device__ __forceinline__ void bulk_wait_all() {
    asm volatile("cp.async.bulk.wait_group 0;" ::: "memory");
}

__global__ void __launch_bounds__(NTHR) fused_kernel(
    const float* __restrict__ Cand,     // [NO, KC, DIM]
    const float* __restrict__ ndist,    // [NO, KC]
    const int*   __restrict__ nind,     // [NO, KC]
    const float* __restrict__ dtrain,   // [NT, DIM]
    const float* __restrict__ W,        // [2*DIM, OUTF]
    const float* __restrict__ A,        // [2*OUTF]
    float*       __restrict__ out)
{
    __shared__ __align__(128) float buf[SLOTS][KC * DIM];     // 45056 B
    __shared__ float sScore[2][KC];
    __shared__ float sRow[2][KC];
    __shared__ int   sInd[2][KC];
    __shared__ __align__(8) unsigned long long mbar[SLOTS];

    const int tid  = threadIdx.x;
    const int w    = tid >> 5;
    const int lane = tid & 31;
    const int bid  = blockIdx.x;
    const int G    = gridDim.x;
    const int gwarp = bid * NWARP + w;
    const int gws   = G * NWARP;

    // rows for this CTA: n = bid + i*G, i in [0, cnt)
    const int cnt = (NO - bid + G - 1) / G;

    // ---- earliest possible TMA prolog: candidate loads depend on nothing ----
    uint64_t pol = 0;
    if (tid == 0) {
        pol = make_policy_evict_first();
#pragma unroll
        for (int s = 0; s < SLOTS; ++s) mb_init(smem_u32(&mbar[s]), 1);
        fence_async_shared();
        const int pre = cnt < AHEAD ? cnt : AHEAD;
        for (int i = 0; i < pre; ++i) {
            const int n = bid + i * G;
            const uint32_t mb = smem_u32(&mbar[i]);
            mb_expect(mb, ROWB);
            bulk_load_pol(smem_u32(&buf[i][0]), Cand + (size_t)n * KC * DIM, ROWB, mb, pol);
        }
    }

    // ---- Phase 0: wa2 ----
    if (gwarp < 2 * DIM) {
        const float* wrow = W + (size_t)gwarp * OUTF;
        const float* a2   = A + OUTF;
        float acc = wrow[lane]      * a2[lane]
                  + wrow[lane + 32] * a2[lane + 32]
                  + wrow[lane + 64] * a2[lane + 64]
                  + wrow[lane + 96] * a2[lane + 96];
#pragma unroll
        for (int off = 16; off; off >>= 1)
            acc += __shfl_down_sync(0xffffffffu, acc, off);
        if (lane == 0) g_wa2[gwarp] = acc;
    }
    if (bid == 0 && tid == 0) {
        atomicExch((unsigned long long*)&g_sumA, 0ull);
        atomicExch((unsigned long long*)&g_sumB, 0ull);
    }

    grid_barrier(G);

    // loop-invariant weight registers (wa2_lo for phase 2, wa2_hi for phase 1)
    const float4* w4g = (const float4*)g_wa2;
    float4 wl0 = w4g[lane],      wl1 = w4g[lane + 32];
    float4 wh0 = w4g[lane + 64], wh1 = w4g[lane + 96];

    // ---- Phase 1: streaming table scan; one warp per row ----
    for (int row = gwarp; row < NT; row += gws) {
        const float4* dp = (const float4*)(dtrain + (size_t)row * DIM);
        float4 a = dp[lane];
        float4 b = dp[lane + 32];
        float dot = a.x*wh0.x + a.y*wh0.y + a.z*wh0.z + a.w*wh0.w
                  + b.x*wh1.x + b.y*wh1.y + b.z*wh1.z + b.w*wh1.w;
        float sum = a.x + a.y + a.z + a.w + b.x + b.y + b.z + b.w;
#pragma unroll
        for (int off = 16; off; off >>= 1) {
            dot += __shfl_down_sync(0xffffffffu, dot, off);
            sum += __shfl_down_sync(0xffffffffu, sum, off);
        }
        if (lane == 0) { g_rowdot[row] = dot; g_rowsum[row] = sum; }
    }

    grid_barrier(2u * G);               // rowdot/rowsum visible

    // ---- Phase 2: pipelined main loop ----
    const size_t ND_OFF = (size_t)NO * KSEL * DIM;
    const size_t NI_OFF = ND_OFF + (size_t)NO * KSEL;
    double lsumA = 0.0, lsumB = 0.0;

    for (int i = 0; i < cnt; ++i) {
        const int n    = bid + i * G;
        const int slot = i & (SLOTS - 1);
        const int ph   = (i >> 2) & 1;
        const int b    = i & 1;

        // prefetch table scalars before the wait
        float rdot = 0.f, rsum = 0.f;
        int   ind  = 0;
        if (lane == 0) {
            ind  = __ldg(nind + n * KC + w);
            rdot = g_rowdot[ind];
            rsum = g_rowsum[ind];
        }

        mb_wait(smem_u32(&mbar[slot]), ph);

        const float4* bp = (const float4*)&buf[slot][w * DIM];
        float4 c0 = bp[lane], c1 = bp[lane + 32];

        float sc = c0.x*wl0.x + c0.y*wl0.y + c0.z*wl0.z + c0.w*wl0.w
                 + c1.x*wl1.x + c1.y*wl1.y + c1.z*wl1.z + c1.w*wl1.w;
#pragma unroll
        for (int off = 16; off; off >>= 1)
            sc += __shfl_down_sync(0xffffffffu, sc, off);
        if (lane == 0) {
            sScore[b][w] = sc + rdot;
            sRow[b][w]   = rsum;
            sInd[b][w]   = ind;
        }

        __syncthreads();

        // only the store thread and the tail warp consume `drop`
        if (tid == 0 || w == NWARP - 1) {
            float minv = sScore[b][0];
            int   drop = 0;
#pragma unroll
            for (int kk = 1; kk < KC; ++kk) {
                float v = sScore[b][kk];
                if (v <= minv) { minv = v; drop = kk; }
            }

            if (tid == 0) {
                // bulk stores: prefix [0, drop) rows, suffix (drop, KC) rows
                char* gdst = (char*)out + (size_t)n * SELB;
                const uint32_t src = smem_u32(&buf[slot][0]);
                const uint32_t pb  = (uint32_t)drop * DIM * 4;
                const uint32_t sb  = (uint32_t)(KSEL - drop) * DIM * 4;
                if (pb) bulk_store_pol(gdst, src, pb, pol);
                if (sb) bulk_store_pol(gdst + pb, src + pb + DIM * 4, sb, pol);
                bulk_commit();
                // reuse safety: the slot loaded next was stored at iter i-1 (one group back)
                bulk_wait_read1();
                const int ip = i + AHEAD;
                if (ip < cnt) {
                    const int np = bid + ip * G;
                    const int sl = ip & (SLOTS - 1);
                    const uint32_t mb = smem_u32(&mbar[sl]);
                    mb_expect(mb, ROWB);
                    bulk_load_pol(smem_u32(&buf[sl][0]), Cand + (size_t)np * KC * DIM, ROWB, mb, pol);
                }
            } else {
                if (lane < KSEL) {
                    const int src = lane + (lane >= drop ? 1 : 0);
                    out[ND_OFF + (size_t)n * KSEL + lane] = ndist[n * KC + src];
                    out[NI_OFF + (size_t)n * KSEL + lane] = (float)sInd[b][src];
                } else if (lane == KSEL) {
                    float sa = 0.f;
#pragma unroll
                    for (int kk = 0; kk < KC; ++kk) if (kk != drop) sa += sRow[b][kk];
                    lsumA += (double)sa;
                    lsumB += (double)sRow[b][drop];
                }
            }
        }
    }

    if (tid == 0) bulk_wait_all();      // all bulk stores drained

    if (w == NWARP - 1 && lane == KSEL) {
        atomicAdd(&g_sumA, lsumA);
        atomicAdd(&g_sumB, lsumB);
    }

    // ---- epilog: last CTA writes scalars + resets barrier state ----
    __syncthreads();
    if (tid == 0) {
        // acq_rel increment: orders the sum atomics above without an L1 flush
        unsigned int prev = atom_acqrel_add(&g_done, 1u);
        if (prev == (unsigned)G - 1) {
            double sA = atomicAdd(&g_sumA, 0.0);
            double sB = atomicAdd(&g_sumB, 0.0);
            const size_t A_OFF = (size_t)NO * KSEL * DIM + 2ull * NO * KSEL;
            out[A_OFF]     = (float)(sA / ((double)NO * KSEL));
            out[A_OFF + 1] = (float)(sB / (double)NO);
            atomicExch(&g_bar, 0u);
            atomicExch(&g_done, 0u);
        }
    }
}

extern "C" void kernel_launch(void* const* d_in, const int* in_sizes, int n_in,
                              void* d_out, int out_size) {
    (void)out_size;
    const float* Cand   = nullptr;
    const float* ndist  = nullptr;
    const int*   nind   = nullptr;
    const float* dtrain = nullptr;
    const float* W      = nullptr;
    const float* A      = nullptr;
    for (int i = 0; i < n_in; ++i) {
        const int s = in_sizes[i];
        if      (s == 56320000) Cand   = (const float*)d_in[i];
        else if (s == 25600000) dtrain = (const float*)d_in[i];
        else if (s == 220000) {
            if (!ndist) ndist = (const float*)d_in[i];
            else        nind  = (const int*)d_in[i];
        }
        else if (s == 65536)    W      = (const float*)d_in[i];
        else if (s == 256)      A      = (const float*)d_in[i];
    }
    float* out = (float*)d_out;

    int dev = 0, nsm = 148, perSM = 0;
    cudaGetDevice(&dev);
    cudaDeviceGetAttribute(&nsm, cudaDevAttrMultiProcessorCount, dev);
    cudaOccupancyMaxActiveBlocksPerMultiprocessor(&perSM, fused_kernel, NTHR, 0);
    if (perSM < 1) perSM = 1;
    int grid = nsm * perSM;
    if (grid > NO) grid = NO;

    fused_kernel<<<grid, NTHR>>>(Cand, ndist, nind, dtrain, W, A, out);
}